// round 15
// baseline (speedup 1.0000x reference)
#include <cuda_runtime.h>
#include <cuda_fp16.h>
#include <math.h>
#include <stdint.h>

#define Bc   4
#define Sc   2048
#define DIN  1024
#define DOUT 1024
#define Hc   16
#define HDc  64
#define MROWS (Bc*Sc)   // 8192

// Scratch (device globals: allocation-free per harness rules)
__device__ __align__(256) __half g_q[Bc*Hc*Sc*HDc];      // [b,h,s,d], pre-scaled 0.125
__device__ __align__(256) __half g_k[Bc*Hc*Sc*HDc];      // [b,h,s,d]
__device__ __align__(256) __half g_v[Bc*Hc*Sc*HDc];      // [b,h,d,s] TRANSPOSED
__device__ __align__(256) __half g_ctx[Bc*Sc*DOUT];      // [b,s,n]
__device__ __align__(256) __half g_xh[MROWS*DIN];        // fp16 x
__device__ __align__(256) __half g_wqkv[3*DIN*DOUT];     // [n' (3072)][k]
__device__ __align__(256) __half g_wo[DIN*DOUT];         // [n][k]

// ---------------------------------------------------------------------------
// helpers
// ---------------------------------------------------------------------------
__device__ __forceinline__ void mma_fp16(float d[4], const unsigned a[4],
                                         unsigned b0, unsigned b1, const float c[4]) {
    asm volatile(
        "mma.sync.aligned.m16n8k16.row.col.f32.f16.f16.f32 "
        "{%0,%1,%2,%3}, {%4,%5,%6,%7}, {%8,%9}, {%10,%11,%12,%13};\n"
        : "=f"(d[0]), "=f"(d[1]), "=f"(d[2]), "=f"(d[3])
        : "r"(a[0]), "r"(a[1]), "r"(a[2]), "r"(a[3]),
          "r"(b0), "r"(b1),
          "f"(c[0]), "f"(c[1]), "f"(c[2]), "f"(c[3]));
}

__device__ __forceinline__ void ldmatrix4(unsigned r[4], uint32_t addr) {
    asm volatile("ldmatrix.sync.aligned.m8n8.x4.shared.b16 {%0,%1,%2,%3}, [%4];"
        : "=r"(r[0]), "=r"(r[1]), "=r"(r[2]), "=r"(r[3]) : "r"(addr));
}

__device__ __forceinline__ unsigned packh2(float lo, float hi) {
    __half2 h = __floats2half2_rn(lo, hi);
    return *(unsigned*)&h;
}

__device__ __forceinline__ void cp_async16(uint32_t smem_addr, const void* gptr) {
    asm volatile("cp.async.cg.shared.global [%0], [%1], 16;\n"
                 :: "r"(smem_addr), "l"(gptr));
}
__device__ __forceinline__ void cp_commit() {
    asm volatile("cp.async.commit_group;\n");
}
template<int N>
__device__ __forceinline__ void cp_wait() {
    asm volatile("cp.async.wait_group %0;\n" :: "n"(N));
}

// ---------------------------------------------------------------------------
// Preprocess 1: x -> fp16
// ---------------------------------------------------------------------------
__global__ void cvt_x_kernel(const float* __restrict__ in,
                             __half* __restrict__ out, int n8) {
    int i = blockIdx.x * blockDim.x + threadIdx.x;
    if (i < n8) {
        const float4* ip = (const float4*)(in + (size_t)i * 8);
        float4 u = ip[0], w = ip[1];
        __half2 h[4] = { __floats2half2_rn(u.x, u.y), __floats2half2_rn(u.z, u.w),
                         __floats2half2_rn(w.x, w.y), __floats2half2_rn(w.z, w.w) };
        *(uint2*)(out + (size_t)i * 8)     = *(uint2*)&h[0];
        *(uint2*)(out + (size_t)i * 8 + 4) = *(uint2*)&h[2];
    }
}

// ---------------------------------------------------------------------------
// Preprocess 2: transpose-pack weights to fp16 [n][k]
// ---------------------------------------------------------------------------
__global__ void pack_wt_kernel(const float* __restrict__ Wq,
                               const float* __restrict__ Wk,
                               const float* __restrict__ Wv,
                               const float* __restrict__ Wo,
                               __half* __restrict__ wqkv,
                               __half* __restrict__ wot) {
    __shared__ float t[32][33];
    int w = blockIdx.z;
    const float* W = (w == 0) ? Wq : (w == 1) ? Wk : (w == 2) ? Wv : Wo;
    int k0 = blockIdx.y * 32, n0 = blockIdx.x * 32;
    int tx = threadIdx.x, ty = threadIdx.y;    // 32 x 8
    #pragma unroll
    for (int r = ty; r < 32; r += 8)
        t[r][tx] = W[(size_t)(k0 + r) * DOUT + n0 + tx];
    __syncthreads();
    __half* dst = (w < 3) ? wqkv + (size_t)w * DIN * DOUT : wot;
    #pragma unroll
    for (int r = ty; r < 32; r += 8)
        dst[(size_t)(n0 + r) * DIN + k0 + tx] = __float2half_rn(t[tx][r]);
}

// ---------------------------------------------------------------------------
// FP16 GEMM, cp.async 4-stage, ldmatrix both operands.
// CTA 256(M) x 128(N), k-chunk 32, 8 warps of 64x64 (wf/mma = 1.0).
// MODE 0: fused QKV -> q (scaled 0.125), k, v (transposed), fp16
// MODE 1: out-proj -> fp32 + bias
// ---------------------------------------------------------------------------
#define GAS 40                        // halves stride (32 data + 8 pad)
#define AST (256*GAS)                 // 10240 halves
#define BST (128*GAS)                 // 5120 halves
#define STAGE_H (AST+BST)             // 15360 halves
#define NSTG 4
#define G_SMEM_BYTES (NSTG*STAGE_H*2) // 122880 B

template<int MODE>
__global__ __launch_bounds__(256, 1)
void gemm_fp16(const __half* __restrict__ A,
               const __half* __restrict__ BW,
               const float* __restrict__ bias,
               __half* __restrict__ outq,
               __half* __restrict__ outk,
               __half* __restrict__ outv,
               float* __restrict__ outf) {
    extern __shared__ __align__(16) char smem_raw[];
    const uint32_t sbase = (uint32_t)__cvta_generic_to_shared(smem_raw);

    const int tid  = threadIdx.x;
    const int warp = tid >> 5, lane = tid & 31;
    const int wm = warp >> 1, wn = warp & 1;     // 4x2 warp grid: 64m x 64n
    const int gid = lane >> 2, tig = lane & 3;

    const int row0 = blockIdx.y * 256;
    const int col0 = blockIdx.x * 128;

    const int lm_row8 = lane & 7;
    const int lm_oct  = lane >> 3;
    const int lm_nhl  = (lm_oct >> 1) * 8;
    const int lm_khl  = (lm_oct & 1) * 8;

    float acc[4][8][4] = {};

    auto issue = [&](int t, int s) {
        uint32_t ab = sbase + (uint32_t)(s * STAGE_H) * 2u;
        uint32_t bb = ab + (uint32_t)AST * 2u;
        #pragma unroll
        for (int l = 0; l < 4; l++) {
            int lin = tid + l * 256;
            int r = lin >> 2, c = (lin & 3) * 8;
            cp_async16(ab + (uint32_t)(r * GAS + c) * 2u,
                       &A[(size_t)(row0 + r) * DIN + t * 32 + c]);
        }
        #pragma unroll
        for (int l = 0; l < 2; l++) {
            int lin = tid + l * 256;
            int r = lin >> 2, c = (lin & 3) * 8;
            cp_async16(bb + (uint32_t)(r * GAS + c) * 2u,
                       &BW[(size_t)(col0 + r) * DIN + t * 32 + c]);
        }
        cp_commit();
    };

    issue(0, 0);
    issue(1, 1);
    issue(2, 2);

    const int NT = DIN / 32;   // 32
    for (int t = 0; t < NT; t++) {
        if (t + 2 < NT)      cp_wait<2>();
        else if (t + 1 < NT) cp_wait<1>();
        else                 cp_wait<0>();
        __syncthreads();
        if (t + 3 < NT) issue(t + 3, (t + 3) & 3);

        uint32_t a_addr0 = sbase + (uint32_t)((t & 3) * STAGE_H) * 2u;
        uint32_t b_addr0 = a_addr0 + (uint32_t)AST * 2u;

        #pragma unroll
        for (int kk = 0; kk < 2; kk++) {
            unsigned af[4][4];
            #pragma unroll
            for (int i = 0; i < 4; i++) {
                uint32_t a = a_addr0 +
                    (uint32_t)((wm * 64 + i * 16 + (lane & 15)) * GAS +
                               kk * 16 + (lane >> 4) * 8) * 2u;
                ldmatrix4(af[i], a);
            }
            #pragma unroll
            for (int jp = 0; jp < 4; jp++) {
                unsigned bm[4];
                uint32_t ba = b_addr0 +
                    (uint32_t)((wn * 64 + jp * 16 + lm_nhl + lm_row8) * GAS +
                               kk * 16 + lm_khl) * 2u;
                ldmatrix4(bm, ba);
                #pragma unroll
                for (int i = 0; i < 4; i++) {
                    mma_fp16(acc[i][2*jp],     af[i], bm[0], bm[1], acc[i][2*jp]);
                    mma_fp16(acc[i][2*jp + 1], af[i], bm[2], bm[3], acc[i][2*jp + 1]);
                }
            }
        }
    }

    // Epilogue
    #pragma unroll
    for (int i = 0; i < 4; i++) {
        #pragma unroll
        for (int rr = 0; rr < 2; rr++) {
            int m = row0 + wm * 64 + i * 16 + gid + rr * 8;
            #pragma unroll
            for (int j = 0; j < 8; j++) {
                int n = col0 + wn * 64 + j * 8 + tig * 2;
                float v0 = acc[i][j][rr * 2 + 0];
                float v1 = acc[i][j][rr * 2 + 1];
                if (MODE == 1) {
                    v0 += bias[n]; v1 += bias[n + 1];
                    *(float2*)&outf[(size_t)m * DOUT + n] = make_float2(v0, v1);
                } else {
                    int which = n >> 10;
                    int nl = n & 1023;
                    int b_ = m >> 11, s_ = m & 2047;
                    int h_ = nl >> 6, d_ = nl & 63;
                    if (which == 2) {
                        size_t base = ((size_t)(b_ * Hc + h_) * HDc + d_) * Sc + s_;
                        outv[base]      = __float2half_rn(v0);
                        outv[base + Sc] = __float2half_rn(v1);
                    } else {
                        if (which == 0) { v0 *= 0.125f; v1 *= 0.125f; }
                        __half* dst = (which == 0) ? outq : outk;
                        *(__half2*)&dst[((size_t)(b_ * Hc + h_) * Sc + s_) * HDc + d_] =
                            __floats2half2_rn(v0, v1);
                    }
                }
            }
        }
    }
}

// ---------------------------------------------------------------------------
// Causal flash attention. CTA = 256 queries, 8 warps, warp tile 32x64
// (wf/mma = 1.5). Q pre-scaled; V pre-transposed. Register softmax.
// Warps fully above the diagonal skip tile compute.
// ---------------------------------------------------------------------------
#define TSH 72
#define Q_HALVES (256*TSH)            // 18432
#define KV_ST (64*TSH)                // 4608 per operand
#define KV_STAGE_H (2*KV_ST)          // 9216
#define ATTN_SMEM_BYTES ((Q_HALVES + 2*KV_STAGE_H)*2)   // 73728 B

__global__ __launch_bounds__(256, 1)
void attn_fp16(const __half* __restrict__ q,
               const __half* __restrict__ k,
               const __half* __restrict__ v,
               __half* __restrict__ ctx) {
    extern __shared__ __align__(16) char smem_raw[];
    const uint32_t sbase = (uint32_t)__cvta_generic_to_shared(smem_raw);

    const int qb   = (gridDim.x - 1) - blockIdx.x;   // heavy tiles first
    const int head = blockIdx.y;
    const int b    = blockIdx.z;
    const int q0   = qb * 256;

    const __half* qp = q + ((size_t)(b * Hc + head) * Sc + q0) * HDc;
    const __half* kb = k + (size_t)(b * Hc + head) * Sc * HDc;
    const __half* vb = v + (size_t)(b * Hc + head) * HDc * Sc;   // [d][s]

    const int tid  = threadIdx.x;
    const int warp = tid >> 5, lane = tid & 31;
    const int gid = lane >> 2, tig = lane & 3;

    const int lm_row8 = lane & 7;
    const int lm_oct  = lane >> 3;
    const int lm_nhl  = (lm_oct >> 1) * 8;
    const int lm_khl  = (lm_oct & 1) * 8;

    auto issue_kv = [&](int jb, int s) {
        const __half* kp = kb + (size_t)jb * 64 * HDc;
        uint32_t kas = sbase + (uint32_t)(Q_HALVES + s * KV_STAGE_H) * 2u;
        uint32_t vas = kas + (uint32_t)KV_ST * 2u;
        #pragma unroll
        for (int l = 0; l < 2; l++) {
            int lin = tid + l * 256;
            int r = lin >> 3, c = (lin & 7) * 8;
            cp_async16(kas + (uint32_t)(r * TSH + c) * 2u, &kp[r * HDc + c]);
            cp_async16(vas + (uint32_t)(r * TSH + c) * 2u,
                       &vb[(size_t)r * Sc + jb * 64 + c]);
        }
    };

    // Q tile 256 x 64 halves
    #pragma unroll
    for (int l = 0; l < 8; l++) {
        int lin = tid + l * 256;
        int r = lin >> 3, c = (lin & 7) * 8;
        cp_async16(sbase + (uint32_t)(r * TSH + c) * 2u, &qp[r * HDc + c]);
    }
    issue_kv(0, 0);
    cp_commit();

    // softmax state: (i, half) -> row warp*32 + i*16 + gid + half*8
    float m_st[2][2] = {{-1e30f, -1e30f}, {-1e30f, -1e30f}};
    float l_st[2][2] = {{0.0f, 0.0f}, {0.0f, 0.0f}};
    float o[2][8][4] = {};

    const int wrow_max = q0 + warp * 32 + 31;   // highest query row of this warp
    const int jb_end = 4 * qb + 3;

    for (int jb = 0; jb <= jb_end; jb++) {
        cp_wait<0>();
        __syncthreads();
        if (jb + 1 <= jb_end) { issue_kv(jb + 1, (jb + 1) & 1); cp_commit(); }

        // warp entirely above the diagonal for this KV tile -> no contribution
        if (jb * 64 > wrow_max) continue;

        uint32_t ks_a = sbase + (uint32_t)(Q_HALVES + (jb & 1) * KV_STAGE_H) * 2u;
        uint32_t vs_a = ks_a + (uint32_t)KV_ST * 2u;

        // ----- S = Q @ K^T : warp tile 32x64 -----
        float s[2][8][4] = {};
        #pragma unroll
        for (int kk = 0; kk < 4; kk++) {
            unsigned af[2][4];
            #pragma unroll
            for (int i = 0; i < 2; i++) {
                uint32_t qa = sbase +
                    (uint32_t)((warp * 32 + i * 16 + (lane & 15)) * TSH +
                               kk * 16 + (lane >> 4) * 8) * 2u;
                ldmatrix4(af[i], qa);
            }
            #pragma unroll
            for (int jp = 0; jp < 4; jp++) {
                unsigned bm[4];
                uint32_t ba = ks_a + (uint32_t)((jp * 16 + lm_nhl + lm_row8) * TSH +
                                                kk * 16 + lm_khl) * 2u;
                ldmatrix4(bm, ba);
                #pragma unroll
                for (int i = 0; i < 2; i++) {
                    mma_fp16(s[i][2*jp],     af[i], bm[0], bm[1], s[i][2*jp]);
                    mma_fp16(s[i][2*jp + 1], af[i], bm[2], bm[3], s[i][2*jp + 1]);
                }
            }
        }

        // ----- causal mask (only near the diagonal) -----
        if (jb * 64 + 63 > q0 + warp * 32) {
            #pragma unroll
            for (int i = 0; i < 2; i++) {
                int rlo = q0 + warp * 32 + i * 16 + gid;
                #pragma unroll
                for (int j = 0; j < 8; j++) {
                    int cbase = jb * 64 + j * 8 + tig * 2;
                    if (cbase     > rlo)     s[i][j][0] = -1e30f;
                    if (cbase + 1 > rlo)     s[i][j][1] = -1e30f;
                    if (cbase     > rlo + 8) s[i][j][2] = -1e30f;
                    if (cbase + 1 > rlo + 8) s[i][j][3] = -1e30f;
                }
            }
        }

        // ----- online softmax + pack P -----
        unsigned pa[2][4][4];
        #pragma unroll
        for (int i = 0; i < 2; i++) {
            float mxl = -1e30f, mxh = -1e30f;
            #pragma unroll
            for (int j = 0; j < 8; j++) {
                mxl = fmaxf(mxl, fmaxf(s[i][j][0], s[i][j][1]));
                mxh = fmaxf(mxh, fmaxf(s[i][j][2], s[i][j][3]));
            }
            mxl = fmaxf(mxl, __shfl_xor_sync(0xFFFFFFFF, mxl, 1));
            mxl = fmaxf(mxl, __shfl_xor_sync(0xFFFFFFFF, mxl, 2));
            mxh = fmaxf(mxh, __shfl_xor_sync(0xFFFFFFFF, mxh, 1));
            mxh = fmaxf(mxh, __shfl_xor_sync(0xFFFFFFFF, mxh, 2));

            float mnl = fmaxf(m_st[i][0], mxl);
            float mnh = fmaxf(m_st[i][1], mxh);
            float scl = __expf(m_st[i][0] - mnl);
            float sch = __expf(m_st[i][1] - mnh);

            float sl = 0.0f, sh = 0.0f;
            #pragma unroll
            for (int j = 0; j < 8; j++) {
                float p0 = __expf(s[i][j][0] - mnl);
                float p1 = __expf(s[i][j][1] - mnl);
                float p2 = __expf(s[i][j][2] - mnh);
                float p3 = __expf(s[i][j][3] - mnh);
                sl += p0 + p1; sh += p2 + p3;
                s[i][j][0] = p0; s[i][j][1] = p1; s[i][j][2] = p2; s[i][j][3] = p3;
            }
            sl += __shfl_xor_sync(0xFFFFFFFF, sl, 1);
            sl += __shfl_xor_sync(0xFFFFFFFF, sl, 2);
            sh += __shfl_xor_sync(0xFFFFFFFF, sh, 1);
            sh += __shfl_xor_sync(0xFFFFFFFF, sh, 2);

            m_st[i][0] = mnl; m_st[i][1] = mnh;
            l_st[i][0] = l_st[i][0] * scl + sl;
            l_st[i][1] = l_st[i][1] * sch + sh;

            #pragma unroll
            for (int t = 0; t < 4; t++) {
                pa[i][t][0] = packh2(s[i][2*t][0],   s[i][2*t][1]);
                pa[i][t][1] = packh2(s[i][2*t][2],   s[i][2*t][3]);
                pa[i][t][2] = packh2(s[i][2*t+1][0], s[i][2*t+1][1]);
                pa[i][t][3] = packh2(s[i][2*t+1][2], s[i][2*t+1][3]);
            }

            #pragma unroll
            for (int j = 0; j < 8; j++) {
                o[i][j][0] *= scl; o[i][j][1] *= scl;
                o[i][j][2] *= sch; o[i][j][3] *= sch;
            }
        }

        // ----- O += P @ V -----
        #pragma unroll
        for (int t = 0; t < 4; t++) {
            #pragma unroll
            for (int jp = 0; jp < 4; jp++) {
                unsigned bm[4];
                uint32_t ba = vs_a + (uint32_t)((jp * 16 + lm_nhl + lm_row8) * TSH +
                                                t * 16 + lm_khl) * 2u;
                ldmatrix4(bm, ba);
                #pragma unroll
                for (int i = 0; i < 2; i++) {
                    mma_fp16(o[i][2*jp],     pa[i][t], bm[0], bm[1], o[i][2*jp]);
                    mma_fp16(o[i][2*jp + 1], pa[i][t], bm[2], bm[3], o[i][2*jp + 1]);
                }
            }
        }
    }

    // ----- Epilogue -----
    #pragma unroll
    for (int i = 0; i < 2; i++) {
        float il0 = 1.0f / l_st[i][0];
        float il1 = 1.0f / l_st[i][1];
        int grow = q0 + warp * 32 + i * 16 + gid;
        #pragma unroll
        for (int j = 0; j < 8; j++) {
            int cl = head * HDc + j * 8 + tig * 2;
            *(__half2*)&ctx[((size_t)b * Sc + grow) * DOUT + cl] =
                __floats2half2_rn(o[i][j][0] * il0, o[i][j][1] * il0);
            *(__half2*)&ctx[((size_t)b * Sc + grow + 8) * DOUT + cl] =
                __floats2half2_rn(o[i][j][2] * il1, o[i][j][3] * il1);
        }
    }
}

// ---------------------------------------------------------------------------
extern "C" void kernel_launch(void* const* d_in, const int* in_sizes, int n_in,
                              void* d_out, int out_size) {
    const float* x  = (const float*)d_in[0];
    const float* Wq = (const float*)d_in[1];
    const float* Wk = (const float*)d_in[2];
    const float* Wv = (const float*)d_in[3];
    const float* Wo = (const float*)d_in[4];
    const float* bo = (const float*)d_in[5];
    float* out = (float*)d_out;

    __half *q, *k, *v, *ctx, *xh, *wqkv, *wo;
    cudaGetSymbolAddress((void**)&q,    g_q);
    cudaGetSymbolAddress((void**)&k,    g_k);
    cudaGetSymbolAddress((void**)&v,    g_v);
    cudaGetSymbolAddress((void**)&ctx,  g_ctx);
    cudaGetSymbolAddress((void**)&xh,   g_xh);
    cudaGetSymbolAddress((void**)&wqkv, g_wqkv);
    cudaGetSymbolAddress((void**)&wo,   g_wo);

    cudaFuncSetAttribute(gemm_fp16<0>,
                         cudaFuncAttributeMaxDynamicSharedMemorySize, G_SMEM_BYTES);
    cudaFuncSetAttribute(gemm_fp16<1>,
                         cudaFuncAttributeMaxDynamicSharedMemorySize, G_SMEM_BYTES);
    cudaFuncSetAttribute(attn_fp16,
                         cudaFuncAttributeMaxDynamicSharedMemorySize, ATTN_SMEM_BYTES);

    // preprocess
    cvt_x_kernel<<<(MROWS * DIN / 8 + 255) / 256, 256>>>(x, xh, MROWS * DIN / 8);
    pack_wt_kernel<<<dim3(32, 32, 4), dim3(32, 8)>>>(Wq, Wk, Wv, Wo, wqkv, wo);

    // fused QKV projection
    gemm_fp16<0><<<dim3(24, 32), 256, G_SMEM_BYTES>>>(
        xh, wqkv, nullptr, q, k, v, nullptr);

    attn_fp16<<<dim3(Sc / 256, Hc, Bc), 256, ATTN_SMEM_BYTES>>>(q, k, v, ctx);

    // output projection + bias (fp32 out)
    gemm_fp16<1><<<dim3(8, 32), 256, G_SMEM_BYTES>>>(
        ctx, wo, bo, nullptr, nullptr, nullptr, out);
}

// round 16
// speedup vs baseline: 1.2402x; 1.2402x over previous
#include <cuda_runtime.h>
#include <cuda_fp16.h>
#include <math.h>
#include <stdint.h>

#define Bc   4
#define Sc   2048
#define DIN  1024
#define DOUT 1024
#define Hc   16
#define HDc  64
#define MROWS (Bc*Sc)   // 8192

// Scratch (device globals: allocation-free per harness rules)
__device__ __align__(256) __half g_q[Bc*Hc*Sc*HDc];      // [b,h,s,d], pre-scaled 0.125
__device__ __align__(256) __half g_k[Bc*Hc*Sc*HDc];      // [b,h,s,d]
__device__ __align__(256) __half g_v[Bc*Hc*Sc*HDc];      // [b,h,d,s] TRANSPOSED
__device__ __align__(256) __half g_ctx[Bc*Sc*DOUT];      // [b,s,n]
__device__ __align__(256) __half g_xh[MROWS*DIN];        // fp16 x
__device__ __align__(256) __half g_wqkv[3*DIN*DOUT];     // [n' (3072)][k]
__device__ __align__(256) __half g_wo[DIN*DOUT];         // [n][k]

// ---------------------------------------------------------------------------
// helpers
// ---------------------------------------------------------------------------
__device__ __forceinline__ void mma_fp16(float d[4], const unsigned a[4],
                                         unsigned b0, unsigned b1, const float c[4]) {
    asm volatile(
        "mma.sync.aligned.m16n8k16.row.col.f32.f16.f16.f32 "
        "{%0,%1,%2,%3}, {%4,%5,%6,%7}, {%8,%9}, {%10,%11,%12,%13};\n"
        : "=f"(d[0]), "=f"(d[1]), "=f"(d[2]), "=f"(d[3])
        : "r"(a[0]), "r"(a[1]), "r"(a[2]), "r"(a[3]),
          "r"(b0), "r"(b1),
          "f"(c[0]), "f"(c[1]), "f"(c[2]), "f"(c[3]));
}

__device__ __forceinline__ void ldmatrix4(unsigned r[4], uint32_t addr) {
    asm volatile("ldmatrix.sync.aligned.m8n8.x4.shared.b16 {%0,%1,%2,%3}, [%4];"
        : "=r"(r[0]), "=r"(r[1]), "=r"(r[2]), "=r"(r[3]) : "r"(addr));
}

__device__ __forceinline__ unsigned packh2(float lo, float hi) {
    __half2 h = __floats2half2_rn(lo, hi);
    return *(unsigned*)&h;
}

__device__ __forceinline__ void cp_async16(uint32_t smem_addr, const void* gptr) {
    asm volatile("cp.async.cg.shared.global [%0], [%1], 16;\n"
                 :: "r"(smem_addr), "l"(gptr));
}
__device__ __forceinline__ void cp_commit() {
    asm volatile("cp.async.commit_group;\n");
}
template<int N>
__device__ __forceinline__ void cp_wait() {
    asm volatile("cp.async.wait_group %0;\n" :: "n"(N));
}

// ---------------------------------------------------------------------------
// Preprocess 1: x -> fp16
// ---------------------------------------------------------------------------
__global__ void cvt_x_kernel(const float* __restrict__ in,
                             __half* __restrict__ out, int n8) {
    int i = blockIdx.x * blockDim.x + threadIdx.x;
    if (i < n8) {
        const float4* ip = (const float4*)(in + (size_t)i * 8);
        float4 u = ip[0], w = ip[1];
        __half2 h[4] = { __floats2half2_rn(u.x, u.y), __floats2half2_rn(u.z, u.w),
                         __floats2half2_rn(w.x, w.y), __floats2half2_rn(w.z, w.w) };
        *(uint2*)(out + (size_t)i * 8)     = *(uint2*)&h[0];
        *(uint2*)(out + (size_t)i * 8 + 4) = *(uint2*)&h[2];
    }
}

// ---------------------------------------------------------------------------
// Preprocess 2: transpose-pack weights to fp16 [n][k]
// ---------------------------------------------------------------------------
__global__ void pack_wt_kernel(const float* __restrict__ Wq,
                               const float* __restrict__ Wk,
                               const float* __restrict__ Wv,
                               const float* __restrict__ Wo,
                               __half* __restrict__ wqkv,
                               __half* __restrict__ wot) {
    __shared__ float t[32][33];
    int w = blockIdx.z;
    const float* W = (w == 0) ? Wq : (w == 1) ? Wk : (w == 2) ? Wv : Wo;
    int k0 = blockIdx.y * 32, n0 = blockIdx.x * 32;
    int tx = threadIdx.x, ty = threadIdx.y;    // 32 x 8
    #pragma unroll
    for (int r = ty; r < 32; r += 8)
        t[r][tx] = W[(size_t)(k0 + r) * DOUT + n0 + tx];
    __syncthreads();
    __half* dst = (w < 3) ? wqkv + (size_t)w * DIN * DOUT : wot;
    #pragma unroll
    for (int r = ty; r < 32; r += 8)
        dst[(size_t)(n0 + r) * DIN + k0 + tx] = __float2half_rn(t[tx][r]);
}

// ---------------------------------------------------------------------------
// FP16 GEMM. CTA 128x128, k-chunk 64, 2-stage cp.async double buffer,
// 8 warps (32m x 64n each), ldmatrix both operands, 2 CTAs/SM.
// MODE 0: fused QKV -> q (scaled 0.125), k, v (transposed), fp16
// MODE 1: out-proj -> fp32 + bias
// ---------------------------------------------------------------------------
#define GAS 72                         // halves stride (64 data + 8 pad)
#define GOP (128*GAS)                  // 9216 halves per operand
#define STAGE_H (2*GOP)                // 18432 halves per stage
#define G_SMEM_BYTES (2*STAGE_H*2)     // 73728 B

template<int MODE, int NTOT>
__global__ __launch_bounds__(256, 2)
void gemm_fp16(const __half* __restrict__ A,
               const __half* __restrict__ BW,
               const float* __restrict__ bias,
               __half* __restrict__ outq,
               __half* __restrict__ outk,
               __half* __restrict__ outv,
               float* __restrict__ outf) {
    extern __shared__ __align__(16) char smem_raw[];
    const uint32_t sbase = (uint32_t)__cvta_generic_to_shared(smem_raw);

    const int tid  = threadIdx.x;
    const int warp = tid >> 5, lane = tid & 31;
    const int wm = warp >> 1, wn = warp & 1;     // 4x2 warp grid: 32m x 64n
    const int gid = lane >> 2, tig = lane & 3;

    const int row0 = blockIdx.y * 128;
    const int col0 = blockIdx.x * 128;

    const int lm_row8 = lane & 7;
    const int lm_oct  = lane >> 3;
    const int lm_nhl  = (lm_oct >> 1) * 8;
    const int lm_khl  = (lm_oct & 1) * 8;

    float acc[2][8][4] = {};

    // load k-chunk t (64 deep) into stage s
    auto issue = [&](int t, int s) {
        uint32_t ab = sbase + (uint32_t)(s * STAGE_H) * 2u;
        uint32_t bb = ab + (uint32_t)GOP * 2u;
        #pragma unroll
        for (int l = 0; l < 4; l++) {
            int lin = tid + l * 256;
            int r = lin >> 3, c = (lin & 7) * 8;
            cp_async16(ab + (uint32_t)(r * GAS + c) * 2u,
                       &A[(size_t)(row0 + r) * DIN + t * 64 + c]);
            cp_async16(bb + (uint32_t)(r * GAS + c) * 2u,
                       &BW[(size_t)(col0 + r) * DIN + t * 64 + c]);
        }
        cp_commit();
    };

    issue(0, 0);

    const int NT = DIN / 64;   // 16
    for (int t = 0; t < NT; t++) {
        cp_wait<0>();
        __syncthreads();
        if (t + 1 < NT) issue(t + 1, (t + 1) & 1);

        uint32_t a_addr0 = sbase + (uint32_t)((t & 1) * STAGE_H) * 2u;
        uint32_t b_addr0 = a_addr0 + (uint32_t)GOP * 2u;

        #pragma unroll
        for (int kk = 0; kk < 4; kk++) {
            unsigned af[2][4];
            #pragma unroll
            for (int i = 0; i < 2; i++) {
                uint32_t a = a_addr0 +
                    (uint32_t)((wm * 32 + i * 16 + (lane & 15)) * GAS +
                               kk * 16 + (lane >> 4) * 8) * 2u;
                ldmatrix4(af[i], a);
            }
            #pragma unroll
            for (int jp = 0; jp < 4; jp++) {
                unsigned bm[4];
                uint32_t ba = b_addr0 +
                    (uint32_t)((wn * 64 + jp * 16 + lm_nhl + lm_row8) * GAS +
                               kk * 16 + lm_khl) * 2u;
                ldmatrix4(bm, ba);
                #pragma unroll
                for (int i = 0; i < 2; i++) {
                    mma_fp16(acc[i][2*jp],     af[i], bm[0], bm[1], acc[i][2*jp]);
                    mma_fp16(acc[i][2*jp + 1], af[i], bm[2], bm[3], acc[i][2*jp + 1]);
                }
            }
        }
    }

    // Epilogue
    #pragma unroll
    for (int i = 0; i < 2; i++) {
        #pragma unroll
        for (int rr = 0; rr < 2; rr++) {
            int m = row0 + wm * 32 + i * 16 + gid + rr * 8;
            #pragma unroll
            for (int j = 0; j < 8; j++) {
                int n = col0 + wn * 64 + j * 8 + tig * 2;
                float v0 = acc[i][j][rr * 2 + 0];
                float v1 = acc[i][j][rr * 2 + 1];
                if (MODE == 1) {
                    v0 += bias[n]; v1 += bias[n + 1];
                    *(float2*)&outf[(size_t)m * DOUT + n] = make_float2(v0, v1);
                } else {
                    int which = n >> 10;
                    int nl = n & 1023;
                    int b_ = m >> 11, s_ = m & 2047;
                    int h_ = nl >> 6, d_ = nl & 63;
                    if (which == 2) {
                        // V transposed [b,h,d,s]
                        size_t base = ((size_t)(b_ * Hc + h_) * HDc + d_) * Sc + s_;
                        outv[base]      = __float2half_rn(v0);
                        outv[base + Sc] = __float2half_rn(v1);
                    } else {
                        if (which == 0) { v0 *= 0.125f; v1 *= 0.125f; }  // fold 1/sqrt(64)
                        __half* dst = (which == 0) ? outq : outk;
                        *(__half2*)&dst[((size_t)(b_ * Hc + h_) * Sc + s_) * HDc + d_] =
                            __floats2half2_rn(v0, v1);
                    }
                }
            }
        }
    }
}

// ---------------------------------------------------------------------------
// Causal flash attention (R11 config: 128-q CTA, 8 warps 16x64, 2 CTA/SM).
// Q pre-scaled; V pre-transposed. ldmatrix K/V fragments, register softmax.
// ---------------------------------------------------------------------------
#define TSH 72
#define Q_HALVES (128*TSH)
#define KV_ST (64*TSH)
#define KV_STAGE_H (2*KV_ST)
#define ATTN_SMEM_BYTES ((Q_HALVES + 2*KV_STAGE_H)*2)   // 55296 B

__global__ __launch_bounds__(256, 2)
void attn_fp16(const __half* __restrict__ q,
               const __half* __restrict__ k,
               const __half* __restrict__ v,
               __half* __restrict__ ctx) {
    extern __shared__ __align__(16) char smem_raw[];
    const uint32_t sbase = (uint32_t)__cvta_generic_to_shared(smem_raw);

    const int qb   = (gridDim.x - 1) - blockIdx.x;   // heavy tiles first
    const int head = blockIdx.y;
    const int b    = blockIdx.z;
    const int q0   = qb * 128;

    const __half* qp = q + ((size_t)(b * Hc + head) * Sc + q0) * HDc;
    const __half* kb = k + (size_t)(b * Hc + head) * Sc * HDc;
    const __half* vb = v + (size_t)(b * Hc + head) * HDc * Sc;   // [d][s]

    const int tid  = threadIdx.x;
    const int warp = tid >> 5, lane = tid & 31;
    const int gid = lane >> 2, tig = lane & 3;

    const int lm_row8 = lane & 7;
    const int lm_oct  = lane >> 3;
    const int lm_nhl  = (lm_oct >> 1) * 8;
    const int lm_khl  = (lm_oct & 1) * 8;

    auto issue_kv = [&](int jb, int s) {
        const __half* kp = kb + (size_t)jb * 64 * HDc;
        uint32_t kas = sbase + (uint32_t)(Q_HALVES + s * KV_STAGE_H) * 2u;
        uint32_t vas = kas + (uint32_t)KV_ST * 2u;
        #pragma unroll
        for (int l = 0; l < 2; l++) {
            int lin = tid + l * 256;
            int r = lin >> 3, c = (lin & 7) * 8;
            cp_async16(kas + (uint32_t)(r * TSH + c) * 2u, &kp[r * HDc + c]);
            cp_async16(vas + (uint32_t)(r * TSH + c) * 2u,
                       &vb[(size_t)r * Sc + jb * 64 + c]);
        }
    };

    // Q tile
    #pragma unroll
    for (int l = 0; l < 4; l++) {
        int lin = tid + l * 256;
        int r = lin >> 3, c = (lin & 7) * 8;
        cp_async16(sbase + (uint32_t)(r * TSH + c) * 2u, &qp[r * HDc + c]);
    }
    issue_kv(0, 0);
    cp_commit();

    float m0 = -1e30f, m1 = -1e30f, l0 = 0.0f, l1 = 0.0f;
    float o[8][4] = {};

    const int jb_end = 2 * qb + 1;
    for (int jb = 0; jb <= jb_end; jb++) {
        cp_wait<0>();
        __syncthreads();
        if (jb + 1 <= jb_end) { issue_kv(jb + 1, (jb + 1) & 1); cp_commit(); }

        uint32_t ks_a = sbase + (uint32_t)(Q_HALVES + (jb & 1) * KV_STAGE_H) * 2u;
        uint32_t vs_a = ks_a + (uint32_t)KV_ST * 2u;

        // ----- S = Q @ K^T : warp tile 16x64 -----
        float s[8][4] = {};
        #pragma unroll
        for (int kk = 0; kk < 4; kk++) {
            unsigned af[4];
            uint32_t qa = sbase + (uint32_t)((warp * 16 + (lane & 15)) * TSH +
                                             kk * 16 + (lane >> 4) * 8) * 2u;
            ldmatrix4(af, qa);
            #pragma unroll
            for (int jp = 0; jp < 4; jp++) {
                unsigned bm[4];
                uint32_t ba = ks_a + (uint32_t)((jp * 16 + lm_nhl + lm_row8) * TSH +
                                                kk * 16 + lm_khl) * 2u;
                ldmatrix4(bm, ba);
                mma_fp16(s[2*jp],     af, bm[0], bm[1], s[2*jp]);
                mma_fp16(s[2*jp + 1], af, bm[2], bm[3], s[2*jp + 1]);
            }
        }

        // ----- causal mask (scale folded into Q) -----
        if (jb >= 2 * qb) {
            int rlo = q0 + warp * 16 + gid;
            #pragma unroll
            for (int j = 0; j < 8; j++) {
                int cbase = jb * 64 + j * 8 + tig * 2;
                if (cbase     > rlo)     s[j][0] = -1e30f;
                if (cbase + 1 > rlo)     s[j][1] = -1e30f;
                if (cbase     > rlo + 8) s[j][2] = -1e30f;
                if (cbase + 1 > rlo + 8) s[j][3] = -1e30f;
            }
        }

        // ----- online softmax in registers -----
        float mxl = -1e30f, mxh = -1e30f;
        #pragma unroll
        for (int j = 0; j < 8; j++) {
            mxl = fmaxf(mxl, fmaxf(s[j][0], s[j][1]));
            mxh = fmaxf(mxh, fmaxf(s[j][2], s[j][3]));
        }
        mxl = fmaxf(mxl, __shfl_xor_sync(0xFFFFFFFF, mxl, 1));
        mxl = fmaxf(mxl, __shfl_xor_sync(0xFFFFFFFF, mxl, 2));
        mxh = fmaxf(mxh, __shfl_xor_sync(0xFFFFFFFF, mxh, 1));
        mxh = fmaxf(mxh, __shfl_xor_sync(0xFFFFFFFF, mxh, 2));

        float mnl = fmaxf(m0, mxl), mnh = fmaxf(m1, mxh);
        float scl = __expf(m0 - mnl), sch = __expf(m1 - mnh);

        float sl = 0.0f, sh = 0.0f;
        #pragma unroll
        for (int j = 0; j < 8; j++) {
            float p0 = __expf(s[j][0] - mnl);
            float p1 = __expf(s[j][1] - mnl);
            float p2 = __expf(s[j][2] - mnh);
            float p3 = __expf(s[j][3] - mnh);
            sl += p0 + p1; sh += p2 + p3;
            s[j][0] = p0; s[j][1] = p1; s[j][2] = p2; s[j][3] = p3;
        }
        sl += __shfl_xor_sync(0xFFFFFFFF, sl, 1);
        sl += __shfl_xor_sync(0xFFFFFFFF, sl, 2);
        sh += __shfl_xor_sync(0xFFFFFFFF, sh, 1);
        sh += __shfl_xor_sync(0xFFFFFFFF, sh, 2);

        m0 = mnl; m1 = mnh;
        l0 = l0 * scl + sl;
        l1 = l1 * sch + sh;

        // pack P into fp16 A-fragments (no shuffles)
        unsigned pa[4][4];
        #pragma unroll
        for (int t = 0; t < 4; t++) {
            pa[t][0] = packh2(s[2*t][0],   s[2*t][1]);
            pa[t][1] = packh2(s[2*t][2],   s[2*t][3]);
            pa[t][2] = packh2(s[2*t+1][0], s[2*t+1][1]);
            pa[t][3] = packh2(s[2*t+1][2], s[2*t+1][3]);
        }

        // rescale O
        #pragma unroll
        for (int j = 0; j < 8; j++) {
            o[j][0] *= scl; o[j][1] *= scl;
            o[j][2] *= sch; o[j][3] *= sch;
        }

        // ----- O += P @ V (V rows = d, cols = s) -----
        #pragma unroll
        for (int t = 0; t < 4; t++) {
            #pragma unroll
            for (int jp = 0; jp < 4; jp++) {
                unsigned bm[4];
                uint32_t ba = vs_a + (uint32_t)((jp * 16 + lm_nhl + lm_row8) * TSH +
                                                t * 16 + lm_khl) * 2u;
                ldmatrix4(bm, ba);
                mma_fp16(o[2*jp],     pa[t], bm[0], bm[1], o[2*jp]);
                mma_fp16(o[2*jp + 1], pa[t], bm[2], bm[3], o[2*jp + 1]);
            }
        }
    }

    // ----- Epilogue -----
    {
        float il0 = 1.0f / l0, il1 = 1.0f / l1;
        int grow = q0 + warp * 16 + gid;
        #pragma unroll
        for (int j = 0; j < 8; j++) {
            int cl = head * HDc + j * 8 + tig * 2;
            *(__half2*)&ctx[((size_t)b * Sc + grow) * DOUT + cl] =
                __floats2half2_rn(o[j][0] * il0, o[j][1] * il0);
            *(__half2*)&ctx[((size_t)b * Sc + grow + 8) * DOUT + cl] =
                __floats2half2_rn(o[j][2] * il1, o[j][3] * il1);
        }
    }
}

// ---------------------------------------------------------------------------
extern "C" void kernel_launch(void* const* d_in, const int* in_sizes, int n_in,
                              void* d_out, int out_size) {
    const float* x  = (const float*)d_in[0];
    const float* Wq = (const float*)d_in[1];
    const float* Wk = (const float*)d_in[2];
    const float* Wv = (const float*)d_in[3];
    const float* Wo = (const float*)d_in[4];
    const float* bo = (const float*)d_in[5];
    float* out = (float*)d_out;

    __half *q, *k, *v, *ctx, *xh, *wqkv, *wo;
    cudaGetSymbolAddress((void**)&q,    g_q);
    cudaGetSymbolAddress((void**)&k,    g_k);
    cudaGetSymbolAddress((void**)&v,    g_v);
    cudaGetSymbolAddress((void**)&ctx,  g_ctx);
    cudaGetSymbolAddress((void**)&xh,   g_xh);
    cudaGetSymbolAddress((void**)&wqkv, g_wqkv);
    cudaGetSymbolAddress((void**)&wo,   g_wo);

    cudaFuncSetAttribute(gemm_fp16<0, 3072>,
                         cudaFuncAttributeMaxDynamicSharedMemorySize, G_SMEM_BYTES);
    cudaFuncSetAttribute(gemm_fp16<1, 1024>,
                         cudaFuncAttributeMaxDynamicSharedMemorySize, G_SMEM_BYTES);
    cudaFuncSetAttribute(attn_fp16,
                         cudaFuncAttributeMaxDynamicSharedMemorySize, ATTN_SMEM_BYTES);

    // preprocess
    cvt_x_kernel<<<(MROWS * DIN / 8 + 255) / 256, 256>>>(x, xh, MROWS * DIN / 8);
    pack_wt_kernel<<<dim3(32, 32, 4), dim3(32, 8)>>>(Wq, Wk, Wv, Wo, wqkv, wo);

    // fused QKV projection
    gemm_fp16<0, 3072><<<dim3(24, 64), 256, G_SMEM_BYTES>>>(
        xh, wqkv, nullptr, q, k, v, nullptr);

    attn_fp16<<<dim3(Sc / 128, Hc, Bc), 256, ATTN_SMEM_BYTES>>>(q, k, v, ctx);

    // output projection + bias (fp32 out)
    gemm_fp16<1, 1024><<<dim3(8, 64), 256, G_SMEM_BYTES>>>(
        ctx, wo, bo, nullptr, nullptr, nullptr, out);
}

// round 17
// speedup vs baseline: 1.2529x; 1.0102x over previous
#include <cuda_runtime.h>
#include <cuda_fp16.h>
#include <math.h>
#include <stdint.h>

#define Bc   4
#define Sc   2048
#define DIN  1024
#define DOUT 1024
#define Hc   16
#define HDc  64
#define MROWS (Bc*Sc)   // 8192

// Scratch (device globals: allocation-free per harness rules)
__device__ __align__(256) __half g_q[Bc*Hc*Sc*HDc];      // [b,h,s,d], pre-scaled 0.125*log2e
__device__ __align__(256) __half g_k[Bc*Hc*Sc*HDc];      // [b,h,s,d]
__device__ __align__(256) __half g_v[Bc*Hc*Sc*HDc];      // [b,h,d,s] TRANSPOSED
__device__ __align__(256) __half g_ctx[Bc*Sc*DOUT];      // [b,s,n]
__device__ __align__(256) __half g_xh[MROWS*DIN];        // fp16 x
__device__ __align__(256) __half g_wqkv[3*DIN*DOUT];     // [n' (3072)][k]
__device__ __align__(256) __half g_wo[DIN*DOUT];         // [n][k]

// ---------------------------------------------------------------------------
// helpers
// ---------------------------------------------------------------------------
__device__ __forceinline__ void mma_fp16(float d[4], const unsigned a[4],
                                         unsigned b0, unsigned b1, const float c[4]) {
    asm volatile(
        "mma.sync.aligned.m16n8k16.row.col.f32.f16.f16.f32 "
        "{%0,%1,%2,%3}, {%4,%5,%6,%7}, {%8,%9}, {%10,%11,%12,%13};\n"
        : "=f"(d[0]), "=f"(d[1]), "=f"(d[2]), "=f"(d[3])
        : "r"(a[0]), "r"(a[1]), "r"(a[2]), "r"(a[3]),
          "r"(b0), "r"(b1),
          "f"(c[0]), "f"(c[1]), "f"(c[2]), "f"(c[3]));
}

__device__ __forceinline__ void ldmatrix4(unsigned r[4], uint32_t addr) {
    asm volatile("ldmatrix.sync.aligned.m8n8.x4.shared.b16 {%0,%1,%2,%3}, [%4];"
        : "=r"(r[0]), "=r"(r[1]), "=r"(r[2]), "=r"(r[3]) : "r"(addr));
}

__device__ __forceinline__ unsigned packh2(float lo, float hi) {
    __half2 h = __floats2half2_rn(lo, hi);
    return *(unsigned*)&h;
}

__device__ __forceinline__ float ex2f(float x) {
    float r;
    asm("ex2.approx.f32 %0, %1;" : "=f"(r) : "f"(x));
    return r;
}

__device__ __forceinline__ void cp_async16(uint32_t smem_addr, const void* gptr) {
    asm volatile("cp.async.cg.shared.global [%0], [%1], 16;\n"
                 :: "r"(smem_addr), "l"(gptr));
}
__device__ __forceinline__ void cp_commit() {
    asm volatile("cp.async.commit_group;\n");
}
template<int N>
__device__ __forceinline__ void cp_wait() {
    asm volatile("cp.async.wait_group %0;\n" :: "n"(N));
}

// ---------------------------------------------------------------------------
// Preprocess 1: x -> fp16
// ---------------------------------------------------------------------------
__global__ void cvt_x_kernel(const float* __restrict__ in,
                             __half* __restrict__ out, int n8) {
    int i = blockIdx.x * blockDim.x + threadIdx.x;
    if (i < n8) {
        const float4* ip = (const float4*)(in + (size_t)i * 8);
        float4 u = ip[0], w = ip[1];
        __half2 h[4] = { __floats2half2_rn(u.x, u.y), __floats2half2_rn(u.z, u.w),
                         __floats2half2_rn(w.x, w.y), __floats2half2_rn(w.z, w.w) };
        *(uint2*)(out + (size_t)i * 8)     = *(uint2*)&h[0];
        *(uint2*)(out + (size_t)i * 8 + 4) = *(uint2*)&h[2];
    }
}

// ---------------------------------------------------------------------------
// Preprocess 2: transpose-pack weights to fp16 [n][k]
// ---------------------------------------------------------------------------
__global__ void pack_wt_kernel(const float* __restrict__ Wq,
                               const float* __restrict__ Wk,
                               const float* __restrict__ Wv,
                               const float* __restrict__ Wo,
                               __half* __restrict__ wqkv,
                               __half* __restrict__ wot) {
    __shared__ float t[32][33];
    int w = blockIdx.z;
    const float* W = (w == 0) ? Wq : (w == 1) ? Wk : (w == 2) ? Wv : Wo;
    int k0 = blockIdx.y * 32, n0 = blockIdx.x * 32;
    int tx = threadIdx.x, ty = threadIdx.y;    // 32 x 8
    #pragma unroll
    for (int r = ty; r < 32; r += 8)
        t[r][tx] = W[(size_t)(k0 + r) * DOUT + n0 + tx];
    __syncthreads();
    __half* dst = (w < 3) ? wqkv + (size_t)w * DIN * DOUT : wot;
    #pragma unroll
    for (int r = ty; r < 32; r += 8)
        dst[(size_t)(n0 + r) * DIN + k0 + tx] = __float2half_rn(t[tx][r]);
}

// ---------------------------------------------------------------------------
// FP16 GEMM (unchanged from R15). CTA 128x128, k-chunk 64, 2-stage,
// 8 warps (32m x 64n), ldmatrix both operands, 2 CTAs/SM.
// MODE 0: fused QKV -> q (scaled 0.125*log2e), k, v (transposed), fp16
// MODE 1: out-proj -> fp32 + bias
// ---------------------------------------------------------------------------
#define QSCALE 0.1803368801111244f    // 0.125 * log2(e)
#define GAS 72                         // halves stride (64 data + 8 pad)
#define GOP (128*GAS)                  // 9216 halves per operand
#define STAGE_H (2*GOP)                // 18432 halves per stage
#define G_SMEM_BYTES (2*STAGE_H*2)     // 73728 B

template<int MODE, int NTOT>
__global__ __launch_bounds__(256, 2)
void gemm_fp16(const __half* __restrict__ A,
               const __half* __restrict__ BW,
               const float* __restrict__ bias,
               __half* __restrict__ outq,
               __half* __restrict__ outk,
               __half* __restrict__ outv,
               float* __restrict__ outf) {
    extern __shared__ __align__(16) char smem_raw[];
    const uint32_t sbase = (uint32_t)__cvta_generic_to_shared(smem_raw);

    const int tid  = threadIdx.x;
    const int warp = tid >> 5, lane = tid & 31;
    const int wm = warp >> 1, wn = warp & 1;     // 4x2 warp grid: 32m x 64n
    const int gid = lane >> 2, tig = lane & 3;

    const int row0 = blockIdx.y * 128;
    const int col0 = blockIdx.x * 128;

    const int lm_row8 = lane & 7;
    const int lm_oct  = lane >> 3;
    const int lm_nhl  = (lm_oct >> 1) * 8;
    const int lm_khl  = (lm_oct & 1) * 8;

    float acc[2][8][4] = {};

    auto issue = [&](int t, int s) {
        uint32_t ab = sbase + (uint32_t)(s * STAGE_H) * 2u;
        uint32_t bb = ab + (uint32_t)GOP * 2u;
        #pragma unroll
        for (int l = 0; l < 4; l++) {
            int lin = tid + l * 256;
            int r = lin >> 3, c = (lin & 7) * 8;
            cp_async16(ab + (uint32_t)(r * GAS + c) * 2u,
                       &A[(size_t)(row0 + r) * DIN + t * 64 + c]);
            cp_async16(bb + (uint32_t)(r * GAS + c) * 2u,
                       &BW[(size_t)(col0 + r) * DIN + t * 64 + c]);
        }
        cp_commit();
    };

    issue(0, 0);

    const int NT = DIN / 64;   // 16
    for (int t = 0; t < NT; t++) {
        cp_wait<0>();
        __syncthreads();
        if (t + 1 < NT) issue(t + 1, (t + 1) & 1);

        uint32_t a_addr0 = sbase + (uint32_t)((t & 1) * STAGE_H) * 2u;
        uint32_t b_addr0 = a_addr0 + (uint32_t)GOP * 2u;

        #pragma unroll
        for (int kk = 0; kk < 4; kk++) {
            unsigned af[2][4];
            #pragma unroll
            for (int i = 0; i < 2; i++) {
                uint32_t a = a_addr0 +
                    (uint32_t)((wm * 32 + i * 16 + (lane & 15)) * GAS +
                               kk * 16 + (lane >> 4) * 8) * 2u;
                ldmatrix4(af[i], a);
            }
            #pragma unroll
            for (int jp = 0; jp < 4; jp++) {
                unsigned bm[4];
                uint32_t ba = b_addr0 +
                    (uint32_t)((wn * 64 + jp * 16 + lm_nhl + lm_row8) * GAS +
                               kk * 16 + lm_khl) * 2u;
                ldmatrix4(bm, ba);
                #pragma unroll
                for (int i = 0; i < 2; i++) {
                    mma_fp16(acc[i][2*jp],     af[i], bm[0], bm[1], acc[i][2*jp]);
                    mma_fp16(acc[i][2*jp + 1], af[i], bm[2], bm[3], acc[i][2*jp + 1]);
                }
            }
        }
    }

    // Epilogue
    #pragma unroll
    for (int i = 0; i < 2; i++) {
        #pragma unroll
        for (int rr = 0; rr < 2; rr++) {
            int m = row0 + wm * 32 + i * 16 + gid + rr * 8;
            #pragma unroll
            for (int j = 0; j < 8; j++) {
                int n = col0 + wn * 64 + j * 8 + tig * 2;
                float v0 = acc[i][j][rr * 2 + 0];
                float v1 = acc[i][j][rr * 2 + 1];
                if (MODE == 1) {
                    v0 += bias[n]; v1 += bias[n + 1];
                    *(float2*)&outf[(size_t)m * DOUT + n] = make_float2(v0, v1);
                } else {
                    int which = n >> 10;
                    int nl = n & 1023;
                    int b_ = m >> 11, s_ = m & 2047;
                    int h_ = nl >> 6, d_ = nl & 63;
                    if (which == 2) {
                        // V transposed [b,h,d,s]
                        size_t base = ((size_t)(b_ * Hc + h_) * HDc + d_) * Sc + s_;
                        outv[base]      = __float2half_rn(v0);
                        outv[base + Sc] = __float2half_rn(v1);
                    } else {
                        if (which == 0) { v0 *= QSCALE; v1 *= QSCALE; }
                        __half* dst = (which == 0) ? outq : outk;
                        *(__half2*)&dst[((size_t)(b_ * Hc + h_) * Sc + s_) * HDc + d_] =
                            __floats2half2_rn(v0, v1);
                    }
                }
            }
        }
    }
}

// ---------------------------------------------------------------------------
// Causal flash attention. 128-q CTA, 8 warps 16x64, 2 CTA/SM.
// KV tiles 128 wide (two 64-halves per barrier). ex2-domain softmax
// (Q pre-scaled by 0.125*log2e). Per-warp skip of fully-masked halves.
// ---------------------------------------------------------------------------
#define TSK 72                         // K tile stride (64 d + 8)
#define TSV 136                        // V tile stride (128 s + 8)
#define Q_HALVES (128*TSK)             // 9216
#define K_ST (128*TSK)                 // 9216 (128 s-rows x 64 d)
#define V_ST (64*TSV)                  // 8704 (64 d-rows x 128 s)
#define KV_STAGE_H (K_ST + V_ST)       // 17920
#define ATTN_SMEM_BYTES ((Q_HALVES + 2*KV_STAGE_H)*2)   // 90112 B

__global__ __launch_bounds__(256, 2)
void attn_fp16(const __half* __restrict__ q,
               const __half* __restrict__ k,
               const __half* __restrict__ v,
               __half* __restrict__ ctx) {
    extern __shared__ __align__(16) char smem_raw[];
    const uint32_t sbase = (uint32_t)__cvta_generic_to_shared(smem_raw);

    const int qb   = (gridDim.x - 1) - blockIdx.x;   // heavy tiles first
    const int head = blockIdx.y;
    const int b    = blockIdx.z;
    const int q0   = qb * 128;

    const __half* qp = q + ((size_t)(b * Hc + head) * Sc + q0) * HDc;
    const __half* kb = k + (size_t)(b * Hc + head) * Sc * HDc;
    const __half* vb = v + (size_t)(b * Hc + head) * HDc * Sc;   // [d][s]

    const int tid  = threadIdx.x;
    const int warp = tid >> 5, lane = tid & 31;
    const int gid = lane >> 2, tig = lane & 3;

    const int lm_row8 = lane & 7;
    const int lm_oct  = lane >> 3;
    const int lm_nhl  = (lm_oct >> 1) * 8;
    const int lm_khl  = (lm_oct & 1) * 8;

    // load 128-wide KV tile jbt into stage s
    auto issue_kv = [&](int jbt, int s) {
        const __half* kp = kb + (size_t)jbt * 128 * HDc;
        uint32_t kas = sbase + (uint32_t)(Q_HALVES + s * KV_STAGE_H) * 2u;
        uint32_t vas = kas + (uint32_t)K_ST * 2u;
        #pragma unroll
        for (int l = 0; l < 4; l++) {
            int lin = tid + l * 256;
            int kr = lin >> 3, kc = (lin & 7) * 8;        // K: 128 rows x 64
            cp_async16(kas + (uint32_t)(kr * TSK + kc) * 2u, &kp[kr * HDc + kc]);
            int vr = lin >> 4, vc = (lin & 15) * 8;       // V: 64 rows x 128
            cp_async16(vas + (uint32_t)(vr * TSV + vc) * 2u,
                       &vb[(size_t)vr * Sc + jbt * 128 + vc]);
        }
    };

    // Q tile 128 x 64
    #pragma unroll
    for (int l = 0; l < 4; l++) {
        int lin = tid + l * 256;
        int r = lin >> 3, c = (lin & 7) * 8;
        cp_async16(sbase + (uint32_t)(r * TSK + c) * 2u, &qp[r * HDc + c]);
    }
    issue_kv(0, 0);
    cp_commit();

    float m0 = -1e30f, m1 = -1e30f, l0 = 0.0f, l1 = 0.0f;
    float o[8][4] = {};

    const int wrow_lo  = q0 + warp * 16;        // lowest query row of warp
    const int wrow_max = wrow_lo + 15;          // highest query row of warp
    const int jbt_end  = qb;                    // 128-wide tiles: 0..qb

    for (int jbt = 0; jbt <= jbt_end; jbt++) {
        cp_wait<0>();
        __syncthreads();
        if (jbt + 1 <= jbt_end) { issue_kv(jbt + 1, (jbt + 1) & 1); cp_commit(); }

        uint32_t ks_a = sbase + (uint32_t)(Q_HALVES + (jbt & 1) * KV_STAGE_H) * 2u;
        uint32_t vs_a = ks_a + (uint32_t)K_ST * 2u;

        #pragma unroll
        for (int half = 0; half < 2; half++) {
            const int colbase = jbt * 128 + half * 64;
            if (colbase > wrow_max) continue;   // fully masked for this warp

            // ----- S = Q @ K^T : warp tile 16x64 -----
            float s[8][4] = {};
            #pragma unroll
            for (int kk = 0; kk < 4; kk++) {
                unsigned af[4];
                uint32_t qa = sbase + (uint32_t)((warp * 16 + (lane & 15)) * TSK +
                                                 kk * 16 + (lane >> 4) * 8) * 2u;
                ldmatrix4(af, qa);
                #pragma unroll
                for (int jp = 0; jp < 4; jp++) {
                    unsigned bm[4];
                    uint32_t ba = ks_a +
                        (uint32_t)((half * 64 + jp * 16 + lm_nhl + lm_row8) * TSK +
                                   kk * 16 + lm_khl) * 2u;
                    ldmatrix4(bm, ba);
                    mma_fp16(s[2*jp],     af, bm[0], bm[1], s[2*jp]);
                    mma_fp16(s[2*jp + 1], af, bm[2], bm[3], s[2*jp + 1]);
                }
            }

            // ----- causal mask (only when the diagonal crosses this half) -----
            if (colbase + 63 > wrow_lo) {
                int rlo = wrow_lo + gid;
                #pragma unroll
                for (int j = 0; j < 8; j++) {
                    int cbase = colbase + j * 8 + tig * 2;
                    if (cbase     > rlo)     s[j][0] = -1e30f;
                    if (cbase + 1 > rlo)     s[j][1] = -1e30f;
                    if (cbase     > rlo + 8) s[j][2] = -1e30f;
                    if (cbase + 1 > rlo + 8) s[j][3] = -1e30f;
                }
            }

            // ----- online softmax (ex2 domain) -----
            float mxl = -1e30f, mxh = -1e30f;
            #pragma unroll
            for (int j = 0; j < 8; j++) {
                mxl = fmaxf(mxl, fmaxf(s[j][0], s[j][1]));
                mxh = fmaxf(mxh, fmaxf(s[j][2], s[j][3]));
            }
            mxl = fmaxf(mxl, __shfl_xor_sync(0xFFFFFFFF, mxl, 1));
            mxl = fmaxf(mxl, __shfl_xor_sync(0xFFFFFFFF, mxl, 2));
            mxh = fmaxf(mxh, __shfl_xor_sync(0xFFFFFFFF, mxh, 1));
            mxh = fmaxf(mxh, __shfl_xor_sync(0xFFFFFFFF, mxh, 2));

            float mnl = fmaxf(m0, mxl), mnh = fmaxf(m1, mxh);
            float scl = ex2f(m0 - mnl), sch = ex2f(m1 - mnh);

            float sl = 0.0f, sh = 0.0f;
            #pragma unroll
            for (int j = 0; j < 8; j++) {
                float p0 = ex2f(s[j][0] - mnl);
                float p1 = ex2f(s[j][1] - mnl);
                float p2 = ex2f(s[j][2] - mnh);
                float p3 = ex2f(s[j][3] - mnh);
                sl += p0 + p1; sh += p2 + p3;
                s[j][0] = p0; s[j][1] = p1; s[j][2] = p2; s[j][3] = p3;
            }
            sl += __shfl_xor_sync(0xFFFFFFFF, sl, 1);
            sl += __shfl_xor_sync(0xFFFFFFFF, sl, 2);
            sh += __shfl_xor_sync(0xFFFFFFFF, sh, 1);
            sh += __shfl_xor_sync(0xFFFFFFFF, sh, 2);

            m0 = mnl; m1 = mnh;
            l0 = l0 * scl + sl;
            l1 = l1 * sch + sh;

            // pack P into fp16 A-fragments
            unsigned pa[4][4];
            #pragma unroll
            for (int t = 0; t < 4; t++) {
                pa[t][0] = packh2(s[2*t][0],   s[2*t][1]);
                pa[t][1] = packh2(s[2*t][2],   s[2*t][3]);
                pa[t][2] = packh2(s[2*t+1][0], s[2*t+1][1]);
                pa[t][3] = packh2(s[2*t+1][2], s[2*t+1][3]);
            }

            // rescale O
            #pragma unroll
            for (int j = 0; j < 8; j++) {
                o[j][0] *= scl; o[j][1] *= scl;
                o[j][2] *= sch; o[j][3] *= sch;
            }

            // ----- O += P @ V (V rows = d, cols = s within 128-wide tile) -----
            #pragma unroll
            for (int t = 0; t < 4; t++) {
                #pragma unroll
                for (int jp = 0; jp < 4; jp++) {
                    unsigned bm[4];
                    uint32_t ba = vs_a +
                        (uint32_t)((jp * 16 + lm_nhl + lm_row8) * TSV +
                                   half * 64 + t * 16 + lm_khl) * 2u;
                    ldmatrix4(bm, ba);
                    mma_fp16(o[2*jp],     pa[t], bm[0], bm[1], o[2*jp]);
                    mma_fp16(o[2*jp + 1], pa[t], bm[2], bm[3], o[2*jp + 1]);
                }
            }
        }
    }

    // ----- Epilogue -----
    {
        float il0 = 1.0f / l0, il1 = 1.0f / l1;
        int grow = q0 + warp * 16 + gid;
        #pragma unroll
        for (int j = 0; j < 8; j++) {
            int cl = head * HDc + j * 8 + tig * 2;
            *(__half2*)&ctx[((size_t)b * Sc + grow) * DOUT + cl] =
                __floats2half2_rn(o[j][0] * il0, o[j][1] * il0);
            *(__half2*)&ctx[((size_t)b * Sc + grow + 8) * DOUT + cl] =
                __floats2half2_rn(o[j][2] * il1, o[j][3] * il1);
        }
    }
}

// ---------------------------------------------------------------------------
extern "C" void kernel_launch(void* const* d_in, const int* in_sizes, int n_in,
                              void* d_out, int out_size) {
    const float* x  = (const float*)d_in[0];
    const float* Wq = (const float*)d_in[1];
    const float* Wk = (const float*)d_in[2];
    const float* Wv = (const float*)d_in[3];
    const float* Wo = (const float*)d_in[4];
    const float* bo = (const float*)d_in[5];
    float* out = (float*)d_out;

    __half *q, *k, *v, *ctx, *xh, *wqkv, *wo;
    cudaGetSymbolAddress((void**)&q,    g_q);
    cudaGetSymbolAddress((void**)&k,    g_k);
    cudaGetSymbolAddress((void**)&v,    g_v);
    cudaGetSymbolAddress((void**)&ctx,  g_ctx);
    cudaGetSymbolAddress((void**)&xh,   g_xh);
    cudaGetSymbolAddress((void**)&wqkv, g_wqkv);
    cudaGetSymbolAddress((void**)&wo,   g_wo);

    cudaFuncSetAttribute(gemm_fp16<0, 3072>,
                         cudaFuncAttributeMaxDynamicSharedMemorySize, G_SMEM_BYTES);
    cudaFuncSetAttribute(gemm_fp16<1, 1024>,
                         cudaFuncAttributeMaxDynamicSharedMemorySize, G_SMEM_BYTES);
    cudaFuncSetAttribute(attn_fp16,
                         cudaFuncAttributeMaxDynamicSharedMemorySize, ATTN_SMEM_BYTES);

    // preprocess
    cvt_x_kernel<<<(MROWS * DIN / 8 + 255) / 256, 256>>>(x, xh, MROWS * DIN / 8);
    pack_wt_kernel<<<dim3(32, 32, 4), dim3(32, 8)>>>(Wq, Wk, Wv, Wo, wqkv, wo);

    // fused QKV projection
    gemm_fp16<0, 3072><<<dim3(24, 64), 256, G_SMEM_BYTES>>>(
        xh, wqkv, nullptr, q, k, v, nullptr);

    attn_fp16<<<dim3(Sc / 128, Hc, Bc), 256, ATTN_SMEM_BYTES>>>(q, k, v, ctx);

    // output projection + bias (fp32 out)
    gemm_fp16<1, 1024><<<dim3(8, 64), 256, G_SMEM_BYTES>>>(
        ctx, wo, bo, nullptr, nullptr, nullptr, out);
}